// round 16
// baseline (speedup 1.0000x reference)
#include <cuda_runtime.h>
#include <math.h>

#define BB 16
#define CC 64
#define NN 1024
#define NH 4
#define FF 15
#define FH 60
#define KK 9
#define ALPHA 0.2f

typedef unsigned long long u64;

// ---------------- scratch (device globals; no allocation) ----------------
__device__ __align__(16) float g_h[BB*CC*NN];      // [b][c][n]
__device__ __align__(16) float g_nsq[BB*NN];       // -0.5*||h_n||^2
__device__ __align__(16) float g_sc[(size_t)BB*NN*NN]; // scores dot+nsq_col [b][i][j] (64MB)
__device__ __align__(16) int   g_idx[BB*NN*KK];
__device__ __align__(16) float g_Wh[BB*NN*FH];     // [b][n][60] (head-major 4x15)
__device__ __align__(16) float g_f1[BB*NN*NH];
__device__ __align__(16) float g_f2[BB*NN*NH];
__device__ __align__(16) float g_den[BB*NN*NH];
__device__ __align__(16) float g_ew[BB*NN*KK*NH];  // cached exp per edge per head
__device__ __align__(16) float g_hcat[BB*NN*FH];
__device__ __align__(16) float g_Who[BB*NN*CC];    // [b][n][64]
__device__ __align__(16) float g_f1o[BB*NN];
__device__ __align__(16) float g_f2o[BB*NN];
__device__ __align__(16) float g_deno[BB*NN];
__device__ __align__(16) float g_ewo[BB*NN*KK];

__global__ void k_dummy() {}

// ---------------- K1: L2 normalize over C (2 threads per node) ----------------
__global__ void k_norm(const float* __restrict__ x) {
    int tid = blockIdx.x * 256 + threadIdx.x;        // [0, 2*B*N)
    int node = tid >> 1, half = tid & 1;
    int b = node >> 10, n = node & 1023;
    const float* xp = x + (size_t)b * CC * NN + half * 32 * NN + n;
    float v[32];
    float s = 0.f;
#pragma unroll
    for (int c = 0; c < 32; c++) { v[c] = xp[c * NN]; s += v[c] * v[c]; }
    s += __shfl_xor_sync(0xFFFFFFFFu, s, 1);
    float nrm = fmaxf(sqrtf(s), 1e-12f);
    float r = 1.0f / nrm;
    float* hp = g_h + (size_t)b * CC * NN + half * 32 * NN + n;
    float s2 = 0.f;
#pragma unroll
    for (int c = 0; c < 32; c++) {
        float w = v[c] * r;
        hp[c * NN] = w;
        s2 += w * w;
    }
    s2 += __shfl_xor_sync(0xFFFFFFFFu, s2, 1);
    if (half == 0) g_nsq[node] = -0.5f * s2;
}

#define TOP9_INSERT(SS, S_ARR, I_ARR, IDX, TH)                          \
    do {                                                                \
        S_ARR[0] = SS; I_ARR[0] = IDX;                                  \
        _Pragma("unroll")                                               \
        for (int _q = 0; _q < 8; _q++) {                                \
            if (S_ARR[_q] > S_ARR[_q + 1]) {                            \
                float _ts = S_ARR[_q]; S_ARR[_q] = S_ARR[_q + 1]; S_ARR[_q + 1] = _ts; \
                int _ti = I_ARR[_q]; I_ARR[_q] = I_ARR[_q + 1]; I_ARR[_q + 1] = _ti;   \
            }                                                           \
        }                                                               \
        TH = S_ARR[0];                                                  \
    } while (0)

// ---------------- K2a: symmetric 128x128 dot GEMM -> g_sc with nsq folded in ----------------
// Upper-triangle tile pairs; dot computed once; stored score = dot + nsq_col at [i][j]
// and (off-diag) [j][i]. smem = As+Bs+nsq (65KB). k3 epilogue on diag blocks.
// grid (36 triangle tiles, 16 b) = 576 blocks, 2 blocks/SM.
extern __shared__ float smem_g[];
__global__ __launch_bounds__(256, 2) void k_gram2(const float* __restrict__ Wheads,
                                                  const float* __restrict__ aheads) {
    float* As   = smem_g;                 // [64][128] 32KB
    float* Bs   = smem_g + 8192;          // [64][128] 32KB
    float* nsqA = smem_g + 16384;         // [128]
    float* nsqB = smem_g + 16512;         // [128]

    // triangle decode: blockIdx.x in [0,36) -> (a, bt), a <= bt
    int a = 0, rem = blockIdx.x;
    while (rem >= 8 - a) { rem -= 8 - a; a++; }
    int bt = a + rem;
    bool diag = (a == bt);

    int b = blockIdx.y;
    int i0 = a * 128;
    int j0 = bt * 128;
    int t = threadIdx.x;
    const float* hb = g_h + (size_t)b * CC * NN;
    const float* nsqb = g_nsq + b * NN;

#pragma unroll
    for (int r = 0; r < 8; r++) {
        int lin = t + r * 256;               // [64][32 f4]
        int c = lin >> 5, pos = lin & 31;
        *(float4*)(As + c * 128 + pos * 4) = *(const float4*)(hb + c * NN + i0 + pos * 4);
        *(float4*)(Bs + c * 128 + pos * 4) = *(const float4*)(hb + c * NN + j0 + pos * 4);
    }
    if (t < 128) {
        nsqA[t] = nsqb[i0 + t];
        nsqB[t] = nsqb[j0 + t];
    }
    __syncthreads();

    int tx = t & 31, ty = t >> 5;            // j group: tx*4, i group: ty*16
    const float* ap = As + ty * 16;
    const float* bp = Bs + tx * 4;
    u64 acc[8][4];
#pragma unroll
    for (int p = 0; p < 8; p++)
#pragma unroll
        for (int j = 0; j < 4; j++) acc[p][j] = 0ull;

#pragma unroll 4
    for (int c = 0; c < 64; c++) {
        ulonglong2 a01 = *(const ulonglong2*)(ap + c * 128);
        ulonglong2 a23 = *(const ulonglong2*)(ap + c * 128 + 4);
        ulonglong2 a45 = *(const ulonglong2*)(ap + c * 128 + 8);
        ulonglong2 a67 = *(const ulonglong2*)(ap + c * 128 + 12);
        u64 apair[8] = { a01.x, a01.y, a23.x, a23.y, a45.x, a45.y, a67.x, a67.y };
        float4 bv = *(const float4*)(bp + c * 128);
        u64 bs_[4];
        asm("mov.b64 %0, {%1, %1};" : "=l"(bs_[0]) : "f"(bv.x));
        asm("mov.b64 %0, {%1, %1};" : "=l"(bs_[1]) : "f"(bv.y));
        asm("mov.b64 %0, {%1, %1};" : "=l"(bs_[2]) : "f"(bv.z));
        asm("mov.b64 %0, {%1, %1};" : "=l"(bs_[3]) : "f"(bv.w));
#pragma unroll
        for (int p = 0; p < 8; p++)
#pragma unroll
            for (int j = 0; j < 4; j++)
                asm("fma.rn.f32x2 %0, %1, %2, %0;" : "+l"(acc[p][j]) : "l"(apair[p]), "l"(bs_[j]));
    }

    float* sc = g_sc + ((size_t)b << 20);
    // direct tile: score = dot + nsq_j (scalar adds during unpack); coalesced float4
    {
        float nq0 = nsqB[tx * 4 + 0];
        float nq1 = nsqB[tx * 4 + 1];
        float nq2 = nsqB[tx * 4 + 2];
        float nq3 = nsqB[tx * 4 + 3];
#pragma unroll
        for (int p = 0; p < 8; p++) {
            float4 lo, hi;
            lo.x = __uint_as_float((unsigned)acc[p][0]) + nq0; hi.x = __uint_as_float((unsigned)(acc[p][0] >> 32)) + nq0;
            lo.y = __uint_as_float((unsigned)acc[p][1]) + nq1; hi.y = __uint_as_float((unsigned)(acc[p][1] >> 32)) + nq1;
            lo.z = __uint_as_float((unsigned)acc[p][2]) + nq2; hi.z = __uint_as_float((unsigned)(acc[p][2] >> 32)) + nq2;
            lo.w = __uint_as_float((unsigned)acc[p][3]) + nq3; hi.w = __uint_as_float((unsigned)(acc[p][3] >> 32)) + nq3;
            *(float4*)(sc + (size_t)(i0 + ty * 16 + 2 * p) * NN + j0 + tx * 4)     = lo;
            *(float4*)(sc + (size_t)(i0 + ty * 16 + 2 * p + 1) * NN + j0 + tx * 4) = hi;
        }
    }
    // transpose tile (off-diag): score = dot + nsq_i (packed pair adds; same IEEE adds)
    if (!diag) {
        u64 ni[8];
#pragma unroll
        for (int p = 0; p < 8; p++) ni[p] = *(const u64*)(nsqA + ty * 16 + 2 * p);
#pragma unroll
        for (int j = 0; j < 4; j++) {
            float* base = sc + (size_t)(j0 + tx * 4 + j) * NN + i0 + ty * 16;
            u64 w[8];
#pragma unroll
            for (int p = 0; p < 8; p++) {
                w[p] = acc[p][j];
                asm("add.rn.f32x2 %0, %0, %1;" : "+l"(w[p]) : "l"(ni[p]));
            }
            ulonglong2 w0; w0.x = w[0]; w0.y = w[1];
            ulonglong2 w1; w1.x = w[2]; w1.y = w[3];
            ulonglong2 w2; w2.x = w[4]; w2.y = w[5];
            ulonglong2 w3; w3.x = w[6]; w3.y = w[7];
            *(ulonglong2*)(base)      = w0;
            *(ulonglong2*)(base + 4)  = w1;
            *(ulonglong2*)(base + 8)  = w2;
            *(ulonglong2*)(base + 12) = w3;
        }
        return;
    }

    // ---- fused k3 epilogue (diagonal blocks only; As intact): Wh, f1/f2, zero den ----
    __syncthreads();
    float* Wc  = Bs;             // [c][h*15+f]  64*60
    float* as2 = Bs + 64 * FH;   // 120
    for (int idx = t; idx < NH * CC * FF; idx += 256) {
        int h = idx / (CC * FF); int rem2 = idx % (CC * FF);
        int c = rem2 / FF; int f = rem2 % FF;
        Wc[c * FH + h * FF + f] = Wheads[idx];
    }
    if (t < NH * 2 * FF) as2[t] = aheads[t];
    __syncthreads();
#pragma unroll
    for (int p = 0; p < 2; p++) {
        int idx = t + p * 256;               // 0..511 = 128 nodes x 4 heads
        int node = idx >> 2, h = idx & 3;
        size_t row = (size_t)b * NN + i0 + node;
        float acc2[FF];
#pragma unroll
        for (int f = 0; f < FF; f++) acc2[f] = 0.f;
#pragma unroll 8
        for (int c = 0; c < CC; c++) {
            float hc = As[c * 128 + node];
#pragma unroll
            for (int f = 0; f < FF; f++) acc2[f] = fmaf(hc, Wc[c * FH + h * FF + f], acc2[f]);
        }
        float* wout = g_Wh + row * FH + h * FF;
#pragma unroll
        for (int f = 0; f < FF; f++) wout[f] = acc2[f];
        float f1 = 0.f, f2 = 0.f;
#pragma unroll
        for (int f = 0; f < FF; f++) {
            f1 = fmaf(acc2[f], as2[h * 2 * FF + f], f1);
            f2 = fmaf(acc2[f], as2[h * 2 * FF + FF + f], f2);
        }
        g_f1[row * NH + h] = f1;
        g_f2[row * NH + h] = f2;
        g_den[row * NH + h] = 0.f;
    }
}

// ---------------- K2b: row scan (8 thr/row, 32 rows/block) + 8-way merge + k4 ----------------
// grid (32, 16) = 512 blocks x 256 threads -> ~3.5 blocks/SM (occupancy fix).
__global__ __launch_bounds__(256) void k_scan() {
    __shared__ u64 keys[256 * 9];        // 18KB
    __shared__ int idxs[32 * 9];
    int t = threadIdx.x;
    int b = blockIdx.y;
    int r0 = blockIdx.x * 32;
    int rowl = t >> 3, q = t & 7;
    const float* sc = g_sc + ((size_t)b << 20) + (size_t)(r0 + rowl) * NN + q * 4;

    float bS[9]; int bI[9];
#pragma unroll
    for (int k = 0; k < 9; k++) { bS[k] = -1e30f; bI[k] = 0; }
    float th = bS[0];
    // 4 batches of 8 independent float4 loads (MLP 8); thread covers j = q*4 + 32*m
    for (int g = 0; g < 4; g++) {
        float4 v[8];
#pragma unroll
        for (int u = 0; u < 8; u++)
            v[u] = *(const float4*)(sc + (g * 8 + u) * 32);
#pragma unroll
        for (int u = 0; u < 8; u++) {
            int j = q * 4 + (g * 8 + u) * 32;
            if (v[u].x > th) TOP9_INSERT(v[u].x, bS, bI, j,     th);
            if (v[u].y > th) TOP9_INSERT(v[u].y, bS, bI, j + 1, th);
            if (v[u].z > th) TOP9_INSERT(v[u].z, bS, bI, j + 2, th);
            if (v[u].w > th) TOP9_INSERT(v[u].w, bS, bI, j + 3, th);
        }
    }
    // dump descending keys (tie -> smaller j wins)
#pragma unroll
    for (int k = 0; k < 9; k++) {
        unsigned u = __float_as_uint(bS[8 - k]);
        u = (u & 0x80000000u) ? ~u : (u | 0x80000000u);
        keys[t * 9 + k] = ((u64)u << 32) | (unsigned)(1023 - bI[8 - k]);
    }
    __syncthreads();
    if (t < 32) {
        const u64* L = keys + (size_t)(8 * t) * 9;
        u64 cur[8]; int p[8];
#pragma unroll
        for (int l = 0; l < 8; l++) { cur[l] = L[l * 9]; p[l] = 1; }
        int* op = g_idx + ((size_t)(b * NN + r0 + t)) * 9;
#pragma unroll
        for (int r = 0; r < 9; r++) {
            u64 m = cur[0]; int ml = 0;
#pragma unroll
            for (int l = 1; l < 8; l++) if (cur[l] > m) { m = cur[l]; ml = l; }
            int jj = 1023 - (int)(m & 0xFFFFFFFFull);
            op[r] = jj;
            idxs[t * 9 + r] = jj;
            cur[ml] = (p[ml] < 9) ? L[ml * 9 + p[ml]] : 0ull;
            p[ml]++;
        }
    }
    __syncthreads();
    // fused k4: head denominators + exp cache for this block's 288 edges
    for (int e = t; e < 32 * KK; e += 256) {
        int lr = e / 9, k = e - lr * 9;
        int rowg = b * NN + r0 + lr;
        int jr = (b << 10) + idxs[lr * 9 + k];
        float4 f1v = *(const float4*)(g_f1 + (size_t)rowg * 4);
        float4 f2v = *(const float4*)(g_f2 + (size_t)jr * 4);
        float* dp = g_den + (size_t)jr * 4;
        float e0 = f1v.x + f2v.x; e0 = e0 > 0.f ? e0 : ALPHA * e0;
        float e1 = f1v.y + f2v.y; e1 = e1 > 0.f ? e1 : ALPHA * e1;
        float e2 = f1v.z + f2v.z; e2 = e2 > 0.f ? e2 : ALPHA * e2;
        float e3 = f1v.w + f2v.w; e3 = e3 > 0.f ? e3 : ALPHA * e3;
        float x0 = __expf(e0), x1 = __expf(e1), x2 = __expf(e2), x3 = __expf(e3);
        *(float4*)(g_ew + ((size_t)rowg * 9 + k) * 4) = make_float4(x0, x1, x2, x3);
        atomicAdd(dp + 0, x0);
        atomicAdd(dp + 1, x1);
        atomicAdd(dp + 2, x2);
        atomicAdd(dp + 3, x3);
    }
}

// ---------------- K5: head aggregation + ELU -> hcat ----------------
__global__ void k5() {
    __shared__ float ws[4 * KK * NH];
    __shared__ int   js[4 * KK];
    int t = threadIdx.x;                 // 240 = 4 nodes x 60
    int row0 = blockIdx.x * 4;
    int bbase = row0 & ~1023;
    if (t < 4 * KK * NH) {
        int local = t / (KK * NH), rem = t % (KK * NH);
        int k = rem >> 2, h = rem & 3;
        int row = row0 + local;
        int jr = bbase + g_idx[row * 9 + k];
        ws[t] = __fdividef(g_ew[((size_t)row * 9 + k) * 4 + h], g_den[(size_t)jr * 4 + h]);
        if (h == 0) js[local * KK + k] = jr;
    }
    __syncthreads();
    int local = t / FH, c = t % FH;
    int row = row0 + local;
    int h = c / FF;
    float acc = 0.f;
#pragma unroll
    for (int k = 0; k < KK; k++)
        acc = fmaf(ws[(local * KK + k) * 4 + h], g_Wh[(size_t)js[local * KK + k] * FH + c], acc);
    g_hcat[(size_t)row * FH + c] = acc > 0.f ? acc : expm1f(acc);
}

// ---------------- K6: W_out GEMM + f1o/f2o, zero deno ----------------
__global__ __launch_bounds__(256) void k6(const float* __restrict__ Wout,
                                          const float* __restrict__ aout) {
    __shared__ float Hc[64 * 61];        // [node][c]
    __shared__ float Wo[FH * CC];
    __shared__ float av[2 * CC];
    int t = threadIdx.x;
    int b = blockIdx.x >> 4;
    int n0 = (blockIdx.x & 15) * 64;
    for (int idx = t; idx < FH * CC; idx += 256) Wo[idx] = Wout[idx];
    if (t < 2 * CC) av[t] = aout[t];
    for (int idx = t; idx < 64 * FH; idx += 256) {
        int node = idx / FH, c = idx % FH;
        Hc[node * 61 + c] = g_hcat[((size_t)(b * NN + n0 + node)) * FH + c];
    }
    __syncthreads();
    int node = t >> 2, q = t & 3;
    size_t row = (size_t)b * NN + n0 + node;
    float acc[16];
#pragma unroll
    for (int f = 0; f < 16; f++) acc[f] = 0.f;
#pragma unroll 6
    for (int c = 0; c < FH; c++) {
        float hv = Hc[node * 61 + c];
#pragma unroll
        for (int f = 0; f < 16; f++)
            acc[f] = fmaf(hv, Wo[c * CC + q * 16 + f], acc[f]);
    }
    float4* wout4 = (float4*)(g_Who + row * CC + q * 16);
#pragma unroll
    for (int p = 0; p < 4; p++)
        wout4[p] = make_float4(acc[4 * p], acc[4 * p + 1], acc[4 * p + 2], acc[4 * p + 3]);
    float f1 = 0.f, f2 = 0.f;
#pragma unroll
    for (int f = 0; f < 16; f++) {
        f1 = fmaf(acc[f], av[q * 16 + f], f1);
        f2 = fmaf(acc[f], av[CC + q * 16 + f], f2);
    }
#pragma unroll
    for (int off = 1; off < 4; off <<= 1) {
        f1 += __shfl_xor_sync(0xFFFFFFFFu, f1, off);
        f2 += __shfl_xor_sync(0xFFFFFFFFu, f2, off);
    }
    if (q == 0) {
        g_f1o[row] = f1;
        g_f2o[row] = f2;
        g_deno[row] = 0.f;
    }
}

// ---------------- K7: output-layer denominators + exp cache — edge-parallel ----------------
__global__ void k7() {
    int e = blockIdx.x * 256 + threadIdx.x;          // [0, B*N*K)
    int row = e / 9;
    int bbase = row & ~1023;
    int jr = bbase + g_idx[e];
    float ee = g_f1o[row] + g_f2o[jr];
    ee = ee > 0.f ? ee : ALPHA * ee;
    float ex = __expf(ee);
    g_ewo[e] = ex;
    atomicAdd(g_deno + jr, ex);
}

// ---------------- K8: out-aggregate + ELU + LReLU + conv1x1 + BN + residual ----------------
__global__ void k8(const float* __restrict__ x, const float* __restrict__ cw,
                   const float* __restrict__ cb, const float* __restrict__ gamma,
                   const float* __restrict__ beta, float* __restrict__ out) {
    __shared__ float cws[CC * 65];
    __shared__ float ys[32 * 65];
    __shared__ float ws[32 * KK];
    __shared__ int   js[32 * KK];
    int t = threadIdx.x;
    int b = blockIdx.x >> 5;
    int n0 = (blockIdx.x & 31) * 32;
    for (int idx = t; idx < CC * CC; idx += 256) {
        int o = idx >> 6, c = idx & 63;
        cws[o * 65 + c] = cw[idx];
    }
    for (int idx = t; idx < 32 * KK; idx += 256) {
        int node = idx / KK, k = idx % KK;
        int row = b * NN + n0 + node;
        int jr = b * NN + g_idx[row * 9 + k];
        ws[idx] = __fdividef(g_ewo[(size_t)row * 9 + k], g_deno[jr]);
        js[idx] = jr;
    }
    __syncthreads();
#pragma unroll
    for (int p = 0; p < 8; p++) {
        int idx = t + p * 256;
        int node = idx >> 6, c = idx & 63;
        float acc = 0.f;
#pragma unroll
        for (int k = 0; k < KK; k++)
            acc = fmaf(ws[node * KK + k], g_Who[(size_t)js[node * KK + k] * CC + c], acc);
        float e = acc > 0.f ? acc : expm1f(acc);     // ELU
        ys[node * 65 + c] = e > 0.f ? e : 0.01f * e; // LeakyReLU(0.01)
    }
    __syncthreads();
    int node = t & 31, og = t >> 5;
    float bnr = 1.0f / sqrtf(1.0f + 1e-5f);
#pragma unroll
    for (int p = 0; p < 8; p++) {
        int o = og * 8 + p;
        float s = cb[o];
        const float* yr = ys + node * 65;
        const float* cr = cws + o * 65;
#pragma unroll
        for (int c = 0; c < CC; c++) s = fmaf(cr[c], yr[c], s);
        s = s * bnr * gamma[o] + beta[o];
        size_t oidx = ((size_t)(b * CC + o)) * NN + n0 + node;
        out[oidx] = s + x[oidx];
    }
}

// ---------------- launch ----------------
extern "C" void kernel_launch(void* const* d_in, const int* in_sizes, int n_in,
                              void* d_out, int out_size) {
    const float* x      = (const float*)d_in[0];
    const float* Wheads = (const float*)d_in[1];
    const float* aheads = (const float*)d_in[2];
    const float* Wout   = (const float*)d_in[3];
    const float* aout   = (const float*)d_in[4];
    const float* convw  = (const float*)d_in[5];
    const float* convb  = (const float*)d_in[6];
    const float* gamma  = (const float*)d_in[7];
    const float* beta   = (const float*)d_in[8];
    float* out = (float*)d_out;

    const int GT_SMEM = (16384 + 256) * 4;  // As+Bs+nsq = 66560B
    static bool attr_set = false;
    if (!attr_set) {
        cudaFuncSetAttribute(k_gram2, cudaFuncAttributeMaxDynamicSharedMemorySize, GT_SMEM);
        attr_set = true;
    }

    k_norm<<<2 * BB * NN / 256, 256>>>(x);                    // launch 0
    k_gram2<<<dim3(36, BB), 256, GT_SMEM>>>(Wheads, aheads);  // launch 1
    k_dummy<<<1, 32>>>();                                     // launch 2
    k_scan<<<dim3(32, BB), 256>>>();                          // launch 3 (profiled slot)
    k5<<<BB * NN / 4, 240>>>();
    k6<<<BB * 16, 256>>>(Wout, aout);
    k7<<<BB * NN * KK / 256, 256>>>();
    k8<<<BB * 32, 256>>>(x, convw, convb, gamma, beta, out);
}

// round 17
// speedup vs baseline: 1.0196x; 1.0196x over previous
#include <cuda_runtime.h>
#include <math.h>

#define BB 16
#define CC 64
#define NN 1024
#define NH 4
#define FF 15
#define FH 60
#define KK 9
#define ALPHA 0.2f

typedef unsigned long long u64;

// ---------------- scratch (device globals; no allocation) ----------------
__device__ __align__(16) float g_h[BB*CC*NN];      // [b][c][n]
__device__ __align__(16) float g_nsq[BB*NN];       // -0.5*||h_n||^2
__device__ __align__(16) float g_sc[(size_t)BB*NN*NN]; // scores dot+nsq_col [b][i][j] (64MB)
__device__ __align__(16) int   g_idx[BB*NN*KK];
__device__ __align__(16) float g_Wh[BB*NN*FH];     // [b][n][60] (head-major 4x15)
__device__ __align__(16) float g_f1[BB*NN*NH];
__device__ __align__(16) float g_f2[BB*NN*NH];
__device__ __align__(16) float g_den[BB*NN*NH];
__device__ __align__(16) float g_ew[BB*NN*KK*NH];  // cached exp per edge per head
__device__ __align__(16) float g_hcat[BB*NN*FH];
__device__ __align__(16) float g_Who[BB*NN*CC];    // [b][n][64]
__device__ __align__(16) float g_f1o[BB*NN];
__device__ __align__(16) float g_f2o[BB*NN];
__device__ __align__(16) float g_deno[BB*NN];
__device__ __align__(16) float g_ewo[BB*NN*KK];

__global__ void k_dummy() {}

// ---------------- K1: L2 normalize over C (2 threads per node) ----------------
__global__ void k_norm(const float* __restrict__ x) {
    int tid = blockIdx.x * 256 + threadIdx.x;        // [0, 2*B*N)
    int node = tid >> 1, half = tid & 1;
    int b = node >> 10, n = node & 1023;
    const float* xp = x + (size_t)b * CC * NN + half * 32 * NN + n;
    float v[32];
    float s = 0.f;
#pragma unroll
    for (int c = 0; c < 32; c++) { v[c] = xp[c * NN]; s += v[c] * v[c]; }
    s += __shfl_xor_sync(0xFFFFFFFFu, s, 1);
    float nrm = fmaxf(sqrtf(s), 1e-12f);
    float r = 1.0f / nrm;
    float* hp = g_h + (size_t)b * CC * NN + half * 32 * NN + n;
    float s2 = 0.f;
#pragma unroll
    for (int c = 0; c < 32; c++) {
        float w = v[c] * r;
        hp[c * NN] = w;
        s2 += w * w;
    }
    s2 += __shfl_xor_sync(0xFFFFFFFFu, s2, 1);
    if (half == 0) g_nsq[node] = -0.5f * s2;
}

#define TOP9_INSERT(SS, S_ARR, I_ARR, IDX, TH)                          \
    do {                                                                \
        S_ARR[0] = SS; I_ARR[0] = IDX;                                  \
        _Pragma("unroll")                                               \
        for (int _q = 0; _q < 8; _q++) {                                \
            if (S_ARR[_q] > S_ARR[_q + 1]) {                            \
                float _ts = S_ARR[_q]; S_ARR[_q] = S_ARR[_q + 1]; S_ARR[_q + 1] = _ts; \
                int _ti = I_ARR[_q]; I_ARR[_q] = I_ARR[_q + 1]; I_ARR[_q + 1] = _ti;   \
            }                                                           \
        }                                                               \
        TH = S_ARR[0];                                                  \
    } while (0)

// ---------------- K2a: symmetric 128x128 dot GEMM -> g_sc with nsq folded in ----------------
// Upper-triangle tile pairs; dot computed once; stored score = dot + nsq_col at [i][j]
// and (off-diag) [j][i]. smem = As+Bs+nsq (65KB). k3 epilogue on diag blocks.
// grid (36 triangle tiles, 16 b) = 576 blocks, 2 blocks/SM.
extern __shared__ float smem_g[];
__global__ __launch_bounds__(256, 2) void k_gram2(const float* __restrict__ Wheads,
                                                  const float* __restrict__ aheads) {
    float* As   = smem_g;                 // [64][128] 32KB
    float* Bs   = smem_g + 8192;          // [64][128] 32KB
    float* nsqA = smem_g + 16384;         // [128]
    float* nsqB = smem_g + 16512;         // [128]

    // triangle decode: blockIdx.x in [0,36) -> (a, bt), a <= bt
    int a = 0, rem = blockIdx.x;
    while (rem >= 8 - a) { rem -= 8 - a; a++; }
    int bt = a + rem;
    bool diag = (a == bt);

    int b = blockIdx.y;
    int i0 = a * 128;
    int j0 = bt * 128;
    int t = threadIdx.x;
    const float* hb = g_h + (size_t)b * CC * NN;
    const float* nsqb = g_nsq + b * NN;

#pragma unroll
    for (int r = 0; r < 8; r++) {
        int lin = t + r * 256;               // [64][32 f4]
        int c = lin >> 5, pos = lin & 31;
        *(float4*)(As + c * 128 + pos * 4) = *(const float4*)(hb + c * NN + i0 + pos * 4);
        *(float4*)(Bs + c * 128 + pos * 4) = *(const float4*)(hb + c * NN + j0 + pos * 4);
    }
    if (t < 128) {
        nsqA[t] = nsqb[i0 + t];
        nsqB[t] = nsqb[j0 + t];
    }
    __syncthreads();

    int tx = t & 31, ty = t >> 5;            // j group: tx*4, i group: ty*16
    const float* ap = As + ty * 16;
    const float* bp = Bs + tx * 4;
    u64 acc[8][4];
#pragma unroll
    for (int p = 0; p < 8; p++)
#pragma unroll
        for (int j = 0; j < 4; j++) acc[p][j] = 0ull;

#pragma unroll 4
    for (int c = 0; c < 64; c++) {
        ulonglong2 a01 = *(const ulonglong2*)(ap + c * 128);
        ulonglong2 a23 = *(const ulonglong2*)(ap + c * 128 + 4);
        ulonglong2 a45 = *(const ulonglong2*)(ap + c * 128 + 8);
        ulonglong2 a67 = *(const ulonglong2*)(ap + c * 128 + 12);
        u64 apair[8] = { a01.x, a01.y, a23.x, a23.y, a45.x, a45.y, a67.x, a67.y };
        float4 bv = *(const float4*)(bp + c * 128);
        u64 bs_[4];
        asm("mov.b64 %0, {%1, %1};" : "=l"(bs_[0]) : "f"(bv.x));
        asm("mov.b64 %0, {%1, %1};" : "=l"(bs_[1]) : "f"(bv.y));
        asm("mov.b64 %0, {%1, %1};" : "=l"(bs_[2]) : "f"(bv.z));
        asm("mov.b64 %0, {%1, %1};" : "=l"(bs_[3]) : "f"(bv.w));
#pragma unroll
        for (int p = 0; p < 8; p++)
#pragma unroll
            for (int j = 0; j < 4; j++)
                asm("fma.rn.f32x2 %0, %1, %2, %0;" : "+l"(acc[p][j]) : "l"(apair[p]), "l"(bs_[j]));
    }

    float* sc = g_sc + ((size_t)b << 20);
    // direct tile: score = dot + nsq_j (scalar adds during unpack); coalesced float4
    {
        float nq0 = nsqB[tx * 4 + 0];
        float nq1 = nsqB[tx * 4 + 1];
        float nq2 = nsqB[tx * 4 + 2];
        float nq3 = nsqB[tx * 4 + 3];
#pragma unroll
        for (int p = 0; p < 8; p++) {
            float4 lo, hi;
            lo.x = __uint_as_float((unsigned)acc[p][0]) + nq0; hi.x = __uint_as_float((unsigned)(acc[p][0] >> 32)) + nq0;
            lo.y = __uint_as_float((unsigned)acc[p][1]) + nq1; hi.y = __uint_as_float((unsigned)(acc[p][1] >> 32)) + nq1;
            lo.z = __uint_as_float((unsigned)acc[p][2]) + nq2; hi.z = __uint_as_float((unsigned)(acc[p][2] >> 32)) + nq2;
            lo.w = __uint_as_float((unsigned)acc[p][3]) + nq3; hi.w = __uint_as_float((unsigned)(acc[p][3] >> 32)) + nq3;
            *(float4*)(sc + (size_t)(i0 + ty * 16 + 2 * p) * NN + j0 + tx * 4)     = lo;
            *(float4*)(sc + (size_t)(i0 + ty * 16 + 2 * p + 1) * NN + j0 + tx * 4) = hi;
        }
    }
    // transpose tile (off-diag): score = dot + nsq_i (packed pair adds; same IEEE adds)
    if (!diag) {
        u64 ni[8];
#pragma unroll
        for (int p = 0; p < 8; p++) ni[p] = *(const u64*)(nsqA + ty * 16 + 2 * p);
#pragma unroll
        for (int j = 0; j < 4; j++) {
            float* base = sc + (size_t)(j0 + tx * 4 + j) * NN + i0 + ty * 16;
            u64 w[8];
#pragma unroll
            for (int p = 0; p < 8; p++) {
                w[p] = acc[p][j];
                asm("add.rn.f32x2 %0, %0, %1;" : "+l"(w[p]) : "l"(ni[p]));
            }
            ulonglong2 w0; w0.x = w[0]; w0.y = w[1];
            ulonglong2 w1; w1.x = w[2]; w1.y = w[3];
            ulonglong2 w2; w2.x = w[4]; w2.y = w[5];
            ulonglong2 w3; w3.x = w[6]; w3.y = w[7];
            *(ulonglong2*)(base)      = w0;
            *(ulonglong2*)(base + 4)  = w1;
            *(ulonglong2*)(base + 8)  = w2;
            *(ulonglong2*)(base + 12) = w3;
        }
        return;
    }

    // ---- fused k3 epilogue (diagonal blocks only; As intact): Wh, f1/f2, zero den ----
    __syncthreads();
    float* Wc  = Bs;             // [c][h*15+f]  64*60
    float* as2 = Bs + 64 * FH;   // 120
    for (int idx = t; idx < NH * CC * FF; idx += 256) {
        int h = idx / (CC * FF); int rem2 = idx % (CC * FF);
        int c = rem2 / FF; int f = rem2 % FF;
        Wc[c * FH + h * FF + f] = Wheads[idx];
    }
    if (t < NH * 2 * FF) as2[t] = aheads[t];
    __syncthreads();
#pragma unroll
    for (int p = 0; p < 2; p++) {
        int idx = t + p * 256;               // 0..511 = 128 nodes x 4 heads
        int node = idx >> 2, h = idx & 3;
        size_t row = (size_t)b * NN + i0 + node;
        float acc2[FF];
#pragma unroll
        for (int f = 0; f < FF; f++) acc2[f] = 0.f;
#pragma unroll 8
        for (int c = 0; c < CC; c++) {
            float hc = As[c * 128 + node];
#pragma unroll
            for (int f = 0; f < FF; f++) acc2[f] = fmaf(hc, Wc[c * FH + h * FF + f], acc2[f]);
        }
        float* wout = g_Wh + row * FH + h * FF;
#pragma unroll
        for (int f = 0; f < FF; f++) wout[f] = acc2[f];
        float f1 = 0.f, f2 = 0.f;
#pragma unroll
        for (int f = 0; f < FF; f++) {
            f1 = fmaf(acc2[f], as2[h * 2 * FF + f], f1);
            f2 = fmaf(acc2[f], as2[h * 2 * FF + FF + f], f2);
        }
        g_f1[row * NH + h] = f1;
        g_f2[row * NH + h] = f2;
        g_den[row * NH + h] = 0.f;
    }
}

// ---------------- K2b: row scan with SHARED row threshold + merge + k4 ----------------
// 4 thr/row, 64 rows/block, grid (16,16). th = max of the 4 lanes' 9th-best
// (refreshed via shfl each 32-value group) — provably safe skip filter.
__global__ __launch_bounds__(256) void k_scan() {
    __shared__ u64 keys[256 * 9];        // 18KB
    __shared__ int idxs[64 * 9];
    int t = threadIdx.x;
    int b = blockIdx.y;
    int r0 = blockIdx.x * 64;
    int rowl = t >> 2, q = t & 3;
    const float* sc = g_sc + ((size_t)b << 20) + (size_t)(r0 + rowl) * NN + q * 4;

    float bS[9]; int bI[9];
#pragma unroll
    for (int k = 0; k < 9; k++) { bS[k] = -1e30f; bI[k] = 0; }
    float th = -1e30f;
    // 8 groups of 32 values (8 batched float4 loads, MLP 8); thread covers j = q*4 + 16*m
    for (int g = 0; g < 8; g++) {
        // refresh shared threshold across the 4 lanes of this row
        {
            float m = bS[0];
            m = fmaxf(m, __shfl_xor_sync(0xFFFFFFFFu, m, 1));
            m = fmaxf(m, __shfl_xor_sync(0xFFFFFFFFu, m, 2));
            th = fmaxf(th, m);
        }
        float4 v[8];
#pragma unroll
        for (int u = 0; u < 8; u++)
            v[u] = *(const float4*)(sc + (g * 8 + u) * 16);
#pragma unroll
        for (int u = 0; u < 8; u++) {
            int j = q * 4 + (g * 8 + u) * 16;
            if (v[u].x > th) { TOP9_INSERT(v[u].x, bS, bI, j,     th); th = fmaxf(th, bS[0]); }
            if (v[u].y > th) { TOP9_INSERT(v[u].y, bS, bI, j + 1, th); th = fmaxf(th, bS[0]); }
            if (v[u].z > th) { TOP9_INSERT(v[u].z, bS, bI, j + 2, th); th = fmaxf(th, bS[0]); }
            if (v[u].w > th) { TOP9_INSERT(v[u].w, bS, bI, j + 3, th); th = fmaxf(th, bS[0]); }
        }
    }
    // dump descending keys (tie -> smaller j wins)
#pragma unroll
    for (int k = 0; k < 9; k++) {
        unsigned u = __float_as_uint(bS[8 - k]);
        u = (u & 0x80000000u) ? ~u : (u | 0x80000000u);
        keys[t * 9 + k] = ((u64)u << 32) | (unsigned)(1023 - bI[8 - k]);
    }
    __syncthreads();
    if (t < 64) {
        const u64* L = keys + (size_t)(4 * t) * 9;
        u64 cur[4]; int p[4];
#pragma unroll
        for (int l = 0; l < 4; l++) { cur[l] = L[l * 9]; p[l] = 1; }
        int* op = g_idx + ((size_t)(b * NN + r0 + t)) * 9;
#pragma unroll
        for (int r = 0; r < 9; r++) {
            u64 m = cur[0]; int ml = 0;
#pragma unroll
            for (int l = 1; l < 4; l++) if (cur[l] > m) { m = cur[l]; ml = l; }
            int jj = 1023 - (int)(m & 0xFFFFFFFFull);
            op[r] = jj;
            idxs[t * 9 + r] = jj;
            cur[ml] = (p[ml] < 9) ? L[ml * 9 + p[ml]] : 0ull;
            p[ml]++;
        }
    }
    __syncthreads();
    // fused k4: head denominators + exp cache for this block's 576 edges
    for (int e = t; e < 64 * KK; e += 256) {
        int lr = e / 9, k = e - lr * 9;
        int rowg = b * NN + r0 + lr;
        int jr = (b << 10) + idxs[lr * 9 + k];
        float4 f1v = *(const float4*)(g_f1 + (size_t)rowg * 4);
        float4 f2v = *(const float4*)(g_f2 + (size_t)jr * 4);
        float* dp = g_den + (size_t)jr * 4;
        float e0 = f1v.x + f2v.x; e0 = e0 > 0.f ? e0 : ALPHA * e0;
        float e1 = f1v.y + f2v.y; e1 = e1 > 0.f ? e1 : ALPHA * e1;
        float e2 = f1v.z + f2v.z; e2 = e2 > 0.f ? e2 : ALPHA * e2;
        float e3 = f1v.w + f2v.w; e3 = e3 > 0.f ? e3 : ALPHA * e3;
        float x0 = __expf(e0), x1 = __expf(e1), x2 = __expf(e2), x3 = __expf(e3);
        *(float4*)(g_ew + ((size_t)rowg * 9 + k) * 4) = make_float4(x0, x1, x2, x3);
        atomicAdd(dp + 0, x0);
        atomicAdd(dp + 1, x1);
        atomicAdd(dp + 2, x2);
        atomicAdd(dp + 3, x3);
    }
}

// ---------------- K5: head aggregation + ELU -> hcat ----------------
__global__ void k5() {
    __shared__ float ws[4 * KK * NH];
    __shared__ int   js[4 * KK];
    int t = threadIdx.x;                 // 240 = 4 nodes x 60
    int row0 = blockIdx.x * 4;
    int bbase = row0 & ~1023;
    if (t < 4 * KK * NH) {
        int local = t / (KK * NH), rem = t % (KK * NH);
        int k = rem >> 2, h = rem & 3;
        int row = row0 + local;
        int jr = bbase + g_idx[row * 9 + k];
        ws[t] = __fdividef(g_ew[((size_t)row * 9 + k) * 4 + h], g_den[(size_t)jr * 4 + h]);
        if (h == 0) js[local * KK + k] = jr;
    }
    __syncthreads();
    int local = t / FH, c = t % FH;
    int row = row0 + local;
    int h = c / FF;
    float acc = 0.f;
#pragma unroll
    for (int k = 0; k < KK; k++)
        acc = fmaf(ws[(local * KK + k) * 4 + h], g_Wh[(size_t)js[local * KK + k] * FH + c], acc);
    g_hcat[(size_t)row * FH + c] = acc > 0.f ? acc : expm1f(acc);
}

// ---------------- K6: W_out GEMM + f1o/f2o, zero deno ----------------
__global__ __launch_bounds__(256) void k6(const float* __restrict__ Wout,
                                          const float* __restrict__ aout) {
    __shared__ float Hc[64 * 61];        // [node][c]
    __shared__ float Wo[FH * CC];
    __shared__ float av[2 * CC];
    int t = threadIdx.x;
    int b = blockIdx.x >> 4;
    int n0 = (blockIdx.x & 15) * 64;
    for (int idx = t; idx < FH * CC; idx += 256) Wo[idx] = Wout[idx];
    if (t < 2 * CC) av[t] = aout[t];
    for (int idx = t; idx < 64 * FH; idx += 256) {
        int node = idx / FH, c = idx % FH;
        Hc[node * 61 + c] = g_hcat[((size_t)(b * NN + n0 + node)) * FH + c];
    }
    __syncthreads();
    int node = t >> 2, q = t & 3;
    size_t row = (size_t)b * NN + n0 + node;
    float acc[16];
#pragma unroll
    for (int f = 0; f < 16; f++) acc[f] = 0.f;
#pragma unroll 6
    for (int c = 0; c < FH; c++) {
        float hv = Hc[node * 61 + c];
#pragma unroll
        for (int f = 0; f < 16; f++)
            acc[f] = fmaf(hv, Wo[c * CC + q * 16 + f], acc[f]);
    }
    float4* wout4 = (float4*)(g_Who + row * CC + q * 16);
#pragma unroll
    for (int p = 0; p < 4; p++)
        wout4[p] = make_float4(acc[4 * p], acc[4 * p + 1], acc[4 * p + 2], acc[4 * p + 3]);
    float f1 = 0.f, f2 = 0.f;
#pragma unroll
    for (int f = 0; f < 16; f++) {
        f1 = fmaf(acc[f], av[q * 16 + f], f1);
        f2 = fmaf(acc[f], av[CC + q * 16 + f], f2);
    }
#pragma unroll
    for (int off = 1; off < 4; off <<= 1) {
        f1 += __shfl_xor_sync(0xFFFFFFFFu, f1, off);
        f2 += __shfl_xor_sync(0xFFFFFFFFu, f2, off);
    }
    if (q == 0) {
        g_f1o[row] = f1;
        g_f2o[row] = f2;
        g_deno[row] = 0.f;
    }
}

// ---------------- K7: output-layer denominators + exp cache — edge-parallel ----------------
__global__ void k7() {
    int e = blockIdx.x * 256 + threadIdx.x;          // [0, B*N*K)
    int row = e / 9;
    int bbase = row & ~1023;
    int jr = bbase + g_idx[e];
    float ee = g_f1o[row] + g_f2o[jr];
    ee = ee > 0.f ? ee : ALPHA * ee;
    float ex = __expf(ee);
    g_ewo[e] = ex;
    atomicAdd(g_deno + jr, ex);
}

// ---------------- K8: out-aggregate + ELU + LReLU + conv1x1 + BN + residual ----------------
__global__ void k8(const float* __restrict__ x, const float* __restrict__ cw,
                   const float* __restrict__ cb, const float* __restrict__ gamma,
                   const float* __restrict__ beta, float* __restrict__ out) {
    __shared__ float cws[CC * 65];
    __shared__ float ys[32 * 65];
    __shared__ float ws[32 * KK];
    __shared__ int   js[32 * KK];
    int t = threadIdx.x;
    int b = blockIdx.x >> 5;
    int n0 = (blockIdx.x & 31) * 32;
    for (int idx = t; idx < CC * CC; idx += 256) {
        int o = idx >> 6, c = idx & 63;
        cws[o * 65 + c] = cw[idx];
    }
    for (int idx = t; idx < 32 * KK; idx += 256) {
        int node = idx / KK, k = idx % KK;
        int row = b * NN + n0 + node;
        int jr = b * NN + g_idx[row * 9 + k];
        ws[idx] = __fdividef(g_ewo[(size_t)row * 9 + k], g_deno[jr]);
        js[idx] = jr;
    }
    __syncthreads();
#pragma unroll
    for (int p = 0; p < 8; p++) {
        int idx = t + p * 256;
        int node = idx >> 6, c = idx & 63;
        float acc = 0.f;
#pragma unroll
        for (int k = 0; k < KK; k++)
            acc = fmaf(ws[node * KK + k], g_Who[(size_t)js[node * KK + k] * CC + c], acc);
        float e = acc > 0.f ? acc : expm1f(acc);     // ELU
        ys[node * 65 + c] = e > 0.f ? e : 0.01f * e; // LeakyReLU(0.01)
    }
    __syncthreads();
    int node = t & 31, og = t >> 5;
    float bnr = 1.0f / sqrtf(1.0f + 1e-5f);
#pragma unroll
    for (int p = 0; p < 8; p++) {
        int o = og * 8 + p;
        float s = cb[o];
        const float* yr = ys + node * 65;
        const float* cr = cws + o * 65;
#pragma unroll
        for (int c = 0; c < CC; c++) s = fmaf(cr[c], yr[c], s);
        s = s * bnr * gamma[o] + beta[o];
        size_t oidx = ((size_t)(b * CC + o)) * NN + n0 + node;
        out[oidx] = s + x[oidx];
    }
}

// ---------------- launch ----------------
extern "C" void kernel_launch(void* const* d_in, const int* in_sizes, int n_in,
                              void* d_out, int out_size) {
    const float* x      = (const float*)d_in[0];
    const float* Wheads = (const float*)d_in[1];
    const float* aheads = (const float*)d_in[2];
    const float* Wout   = (const float*)d_in[3];
    const float* aout   = (const float*)d_in[4];
    const float* convw  = (const float*)d_in[5];
    const float* convb  = (const float*)d_in[6];
    const float* gamma  = (const float*)d_in[7];
    const float* beta   = (const float*)d_in[8];
    float* out = (float*)d_out;

    const int GT_SMEM = (16384 + 256) * 4;  // As+Bs+nsq = 66560B
    static bool attr_set = false;
    if (!attr_set) {
        cudaFuncSetAttribute(k_gram2, cudaFuncAttributeMaxDynamicSharedMemorySize, GT_SMEM);
        attr_set = true;
    }

    k_norm<<<2 * BB * NN / 256, 256>>>(x);                    // launch 0
    k_gram2<<<dim3(36, BB), 256, GT_SMEM>>>(Wheads, aheads);  // launch 1
    k_dummy<<<1, 32>>>();                                     // launch 2
    k_scan<<<dim3(16, BB), 256>>>();                          // launch 3 (profiled slot)
    k5<<<BB * NN / 4, 240>>>();
    k6<<<BB * 16, 256>>>(Wout, aout);
    k7<<<BB * NN * KK / 256, 256>>>();
    k8<<<BB * 32, 256>>>(x, convw, convb, gamma, beta, out);
}